// round 6
// baseline (speedup 1.0000x reference)
#include <cuda_runtime.h>

// ProtoLayer (Kendall rank correlation) — fused bit-pack + popcount, fine-grained.
//
// B=4, Q=75, P=5, D=640. n_pairs = 640*639/2 = 204480.
// Pair set (order-free): all unordered pairs at circular distance 1..320,
// distance-320 half deduped. Per-thread packing (thread i, r=i&31, tbase=i&~31):
//   word j (j=0..10), bit m:  x[tbase + j*32 + m] > x[i]   (circular, xs duplicated)
//   word 0 masked to m>r (dist>=1); word 10 masked to m<=r (dist<=320),
//   with bit m==r dropped for i>=320 (dedup of the distance-320 pair).
// Masked slots are 0 in BOTH q and p words -> contribute 0 to popc(xor).
// Ties dropped (continuous gaussian inputs).
//   sum_pairs sq*sp = NPAIRS - 2*popc(Gq ^ Gp)

#define DIM     640
#define BB      4
#define QQ      75
#define PP      5
#define NQ      (BB * QQ)     // 300
#define NP      (BB * PP)     // 20
#define NJ      11            // words per thread
#define NPAIRS  204480
#define QUARTER 160           // threads per tau block (4 blocks per query)

__device__ __align__(16) unsigned g_pbits[NP][NJ * DIM];   // 0.56 MB, L2-resident
__device__ int g_acc[NQ][PP];    // zero-init; restored to zero by finalizer each run
__device__ int g_cnt[NQ];        // zero-init; restored to zero by finalizer each run

// Build the NJ bit-words for element index i. 4 independent OR chains per word.
__device__ __forceinline__ void build_words(const float* __restrict__ xs,
                                            int i, float xi, unsigned w[NJ])
{
    const int r     = i & 31;
    const int tbase = i & ~31;
#pragma unroll
    for (int j = 0; j < NJ; j++) {
        const float4* __restrict__ ch = (const float4*)(xs + tbase + j * 32);
        unsigned b0 = 0, b1 = 0, b2 = 0, b3 = 0;
#pragma unroll
        for (int c = 0; c < 8; c++) {
            const float4 v = ch[c];              // LDS.128, warp-uniform (broadcast)
            if (v.x > xi) b0 |= (1u << (4 * c));
            if (v.y > xi) b1 |= (2u << (4 * c));
            if (v.z > xi) b2 |= (4u << (4 * c));
            if (v.w > xi) b3 |= (8u << (4 * c));
        }
        w[j] = (b0 | b1) | (b2 | b3);
    }
    w[0]  &= ~((2u << r) - 1u);                               // keep dist >= 1
    w[10] &= (i < 320) ? ((2u << r) - 1u) : ((1u << r) - 1u); // dist <= 320, dedup
}

// grid = 20 (one block per proto vector), block = 640.
__global__ __launch_bounds__(DIM) void proto_build_kernel(const float* __restrict__ pf)
{
    __shared__ __align__(16) float xs[2 * DIM];
    const int vec = blockIdx.x;
    const int i   = threadIdx.x;

    const float xi = pf[(size_t)vec * DIM + i];
    xs[i]       = xi;
    xs[i + DIM] = xi;
    __syncthreads();

    unsigned w[NJ];
    build_words(xs, i, xi, w);
#pragma unroll
    for (int j = 0; j < NJ; j++) g_pbits[vec][j * DIM + i] = w[j];
}

// grid = NQ*4 (4 quarter-blocks per query), block = 160 threads.
__global__ __launch_bounds__(QUARTER) void tau_kernel(const float* __restrict__ qf,
                                                      float* __restrict__ out)
{
    __shared__ __align__(16) float xs[2 * DIM];
    __shared__ int s_part[PP][QUARTER / 32];
    __shared__ int s_last;

    const int bq = blockIdx.x >> 2;            // query index (b*QQ + q)
    const int b  = bq / QQ;
    const int i  = ((blockIdx.x & 3) * QUARTER) + threadIdx.x;   // element index
    const int tid = threadIdx.x;

    // cooperative load of the full row (duplicated for circular indexing)
    const float* __restrict__ row = qf + (size_t)bq * DIM;
#pragma unroll
    for (int k = tid; k < DIM; k += QUARTER) {
        const float v = row[k];
        xs[k] = v;  xs[k + DIM] = v;
    }
    __syncthreads();

    const float xi = xs[i];
    unsigned w[NJ];
    build_words(xs, i, xi, w);

    int ds[PP] = {0, 0, 0, 0, 0};
#pragma unroll
    for (int p = 0; p < PP; p++) {
        const unsigned* __restrict__ pb = g_pbits[b * PP + p];
#pragma unroll
        for (int j = 0; j < NJ; j++)
            ds[p] += __popc(w[j] ^ pb[j * DIM + i]);   // coalesced LDG.32
    }

    const int warp = tid >> 5;
#pragma unroll
    for (int p = 0; p < PP; p++) {
        int c = ds[p];
#pragma unroll
        for (int o = 16; o; o >>= 1) c += __shfl_down_sync(0xffffffffu, c, o);
        if ((tid & 31) == 0) s_part[p][warp] = c;
    }
    __syncthreads();

    if (tid < PP) {
        int c = 0;
#pragma unroll
        for (int k = 0; k < QUARTER / 32; k++) c += s_part[tid][k];
        atomicAdd(&g_acc[bq][tid], c);
    }
    __threadfence();
    __syncthreads();

    if (tid == 0) s_last = (atomicAdd(&g_cnt[bq], 1) == 3);
    __syncthreads();

    if (s_last) {                               // last quarter finalizes + resets
        if (tid < PP) {
            const int s = atomicExch(&g_acc[bq][tid], 0);      // read + re-zero
            out[bq * PP + tid] = (float)(NPAIRS - 2 * s) / (float)NPAIRS;
        }
        if (tid == 0) atomicExch(&g_cnt[bq], 0);               // re-zero counter
    }
}

extern "C" void kernel_launch(void* const* d_in, const int* in_sizes, int n_in,
                              void* d_out, int out_size)
{
    const float* qf = (const float*)d_in[0];   // query_feat (4,75,640)
    const float* pf = (const float*)d_in[1];   // proto_feat (4,5,640)
    if (n_in >= 2 && in_sizes[0] < in_sizes[1]) {   // defensive: query is larger
        const float* t = qf; qf = pf; pf = t;
    }

    proto_build_kernel<<<NP, DIM>>>(pf);
    tau_kernel<<<NQ * 4, QUARTER>>>(qf, (float*)d_out);
}

// round 7
// speedup vs baseline: 1.1622x; 1.1622x over previous
#include <cuda_runtime.h>

// ProtoLayer (Kendall rank correlation) — fused bit-pack + popcount, j-sliced.
//
// B=4, Q=75, P=5, D=640. n_pairs = 640*639/2 = 204480.
// Pair set (order-free): all unordered pairs at circular distance 1..320,
// distance-320 half deduped. Per-thread packing (thread i, r=i&31, tbase=i&~31):
//   word j (j=0..10), bit m:  x[tbase + j*32 + m] > x[i]   (circular, xs duplicated)
//   word 0 masked to m>r (dist>=1); word 10 masked to m<=r (dist<=320),
//   with bit m==r dropped for i>=320 (dedup of the distance-320 pair).
// Masked slots are 0 in BOTH q and p words -> contribute 0 to popc(xor).
// Ties dropped (continuous gaussian inputs).
//   sum_pairs sq*sp = NPAIRS - 2*popc(Gq ^ Gp)
//
// Parallelism: each query is handled by TWO blocks (word slices j=0..5 and
// j=6..10) that accumulate into a global int accumulator; the last block per
// query finalizes the output and resets the accumulator (graph-replay safe).

#define DIM     640
#define BB      4
#define QQ      75
#define PP      5
#define NQ      (BB * QQ)     // 300
#define NP      (BB * PP)     // 20
#define NJ      11            // words per element
#define NPAIRS  204480

__device__ __align__(16) unsigned g_pbits[NP][NJ * DIM];   // 0.56 MB, L2-resident
__device__ int g_acc[NQ][PP];    // zero-init; re-zeroed by finalizer each run
__device__ int g_cnt[NQ];        // zero-init; re-zeroed by finalizer each run

// Build words j = J0 .. J0+JN-1 for element i. 4 independent OR chains per word.
template <int J0, int JN>
__device__ __forceinline__ void build_slice(const float* __restrict__ xs,
                                            int i, float xi, unsigned w[JN])
{
    const int r     = i & 31;
    const int tbase = i & ~31;
#pragma unroll
    for (int jj = 0; jj < JN; jj++) {
        const float4* __restrict__ ch = (const float4*)(xs + tbase + (J0 + jj) * 32);
        unsigned b0 = 0, b1 = 0, b2 = 0, b3 = 0;
#pragma unroll
        for (int c = 0; c < 8; c++) {
            const float4 v = ch[c];              // LDS.128, warp-uniform broadcast
            if (v.x > xi) b0 |= (1u << (4 * c));
            if (v.y > xi) b1 |= (2u << (4 * c));
            if (v.z > xi) b2 |= (4u << (4 * c));
            if (v.w > xi) b3 |= (8u << (4 * c));
        }
        w[jj] = (b0 | b1) | (b2 | b3);
    }
    if (J0 == 0)
        w[0] &= ~((2u << r) - 1u);                                   // dist >= 1
    if (J0 + JN == NJ)
        w[JN - 1] &= (i < 320) ? ((2u << r) - 1u) : ((1u << r) - 1u); // dist <= 320, dedup
}

// Build slice + XOR/popcount against the 5 protos of batch b.
template <int J0, int JN>
__device__ __forceinline__ void slice_popc(const float* __restrict__ xs,
                                           int i, float xi, int b, int ds[PP])
{
    unsigned w[JN];
    build_slice<J0, JN>(xs, i, xi, w);
#pragma unroll
    for (int p = 0; p < PP; p++) {
        const unsigned* __restrict__ pb = g_pbits[b * PP + p];
#pragma unroll
        for (int jj = 0; jj < JN; jj++)
            ds[p] += __popc(w[jj] ^ pb[(J0 + jj) * DIM + i]);   // coalesced LDG.32
    }
}

// grid = (NP, 2) — one block per (proto vector, word-slice), block = 640.
__global__ __launch_bounds__(DIM) void proto_build_kernel(const float* __restrict__ pf)
{
    __shared__ __align__(16) float xs[2 * DIM];
    const int vec = blockIdx.x;
    const int i   = threadIdx.x;

    const float xi = pf[(size_t)vec * DIM + i];
    xs[i]       = xi;
    xs[i + DIM] = xi;
    __syncthreads();

    if (blockIdx.y == 0) {
        unsigned w[6];
        build_slice<0, 6>(xs, i, xi, w);
#pragma unroll
        for (int jj = 0; jj < 6; jj++) g_pbits[vec][jj * DIM + i] = w[jj];
    } else {
        unsigned w[5];
        build_slice<6, 5>(xs, i, xi, w);
#pragma unroll
        for (int jj = 0; jj < 5; jj++) g_pbits[vec][(6 + jj) * DIM + i] = w[jj];
    }
}

// grid = (NQ, 2) — one block per (query, word-slice), block = 640.
__global__ __launch_bounds__(DIM) void tau_kernel(const float* __restrict__ qf,
                                                  float* __restrict__ out)
{
    __shared__ __align__(16) float xs[2 * DIM];
    __shared__ int s_part[PP][DIM / 32];
    __shared__ int s_last;

    const int bq = blockIdx.x;                 // query index (b*QQ + q)
    const int b  = bq / QQ;
    const int i  = threadIdx.x;

    const float xi = qf[(size_t)bq * DIM + i];
    xs[i]       = xi;
    xs[i + DIM] = xi;
    __syncthreads();

    int ds[PP] = {0, 0, 0, 0, 0};
    if (blockIdx.y == 0) slice_popc<0, 6>(xs, i, xi, b, ds);
    else                 slice_popc<6, 5>(xs, i, xi, b, ds);

    const int warp = i >> 5;
#pragma unroll
    for (int p = 0; p < PP; p++) {
        int c = ds[p];
#pragma unroll
        for (int o = 16; o; o >>= 1) c += __shfl_down_sync(0xffffffffu, c, o);
        if ((i & 31) == 0) s_part[p][warp] = c;
    }
    __syncthreads();

    if (i < PP) {
        int c = 0;
#pragma unroll
        for (int k = 0; k < DIM / 32; k++) c += s_part[i][k];
        atomicAdd(&g_acc[bq][i], c);
    }
    __threadfence();
    __syncthreads();

    if (i == 0) s_last = (atomicAdd(&g_cnt[bq], 1) == 1);   // 2 blocks per query
    __syncthreads();

    if (s_last) {                              // last slice finalizes + resets
        if (i < PP) {
            const int s = atomicExch(&g_acc[bq][i], 0);     // read + re-zero
            out[bq * PP + i] = (float)(NPAIRS - 2 * s) / (float)NPAIRS;
        }
        if (i == 0) atomicExch(&g_cnt[bq], 0);              // re-zero counter
    }
}

extern "C" void kernel_launch(void* const* d_in, const int* in_sizes, int n_in,
                              void* d_out, int out_size)
{
    const float* qf = (const float*)d_in[0];   // query_feat (4,75,640)
    const float* pf = (const float*)d_in[1];   // proto_feat (4,5,640)
    if (n_in >= 2 && in_sizes[0] < in_sizes[1]) {   // defensive: query is larger
        const float* t = qf; qf = pf; pf = t;
    }

    proto_build_kernel<<<dim3(NP, 2), DIM>>>(pf);
    tau_kernel<<<dim3(NQ, 2), DIM>>>(qf, (float*)d_out);
}